// round 1
// baseline (speedup 1.0000x reference)
#include <cuda_runtime.h>
#include <math.h>

#define BB 4
#define CC 64
#define HH 128
#define WW 128
#define OO 64
#define KK 3
#define K2 9

// ---------------- scratch (device globals; no allocation allowed) ------------
__device__ float g_xT[BB*HH*WW*CC];     // x transposed to (B,H,W,C)   ~16.8MB
__device__ float g_off[BB*HH*WW*18];    // per-pixel packed offsets (9 y, 9 x)
__device__ float g_mm [BB*HH*WW];       // per-pixel modulation mean
__device__ float g_w3 [K2*CC*OO];       // weight reorganized [k][c][o]

// ---------------- kernel 0: NCHW -> NHWC transpose ---------------------------
__global__ void k_transpose(const float* __restrict__ x) {
    int b = blockIdx.x >> 7;        // gridDim.x = B*H = 512
    int h = blockIdx.x & 127;
    __shared__ float tile[CC][WW + 1];
    for (int idx = threadIdx.x; idx < CC * WW; idx += blockDim.x) {
        int c = idx >> 7, w = idx & 127;
        tile[c][w] = x[((b * CC + c) * HH + h) * WW + w];
    }
    __syncthreads();
    for (int idx = threadIdx.x; idx < CC * WW; idx += blockDim.x) {
        int w = idx >> 6, c = idx & 63;
        g_xT[((b * HH + h) * WW + w) * CC + c] = tile[c][w];
    }
}

// ---------------- kernel 1: weight reorg (O,C,3,3) -> [k][c][o] --------------
__global__ void k_wreorg(const float* __restrict__ weight) {
    for (int idx = blockIdx.x * blockDim.x + threadIdx.x; idx < K2 * CC * OO;
         idx += gridDim.x * blockDim.x) {
        int k = idx / (CC * OO);
        int r = idx % (CC * OO);
        int c = r / OO;
        int o = r % OO;
        g_w3[idx] = weight[(o * CC + c) * K2 + k];
    }
}

// ---------------- kernel 2: fused offset(18) + mod(9) 3x3 conv ---------------
#define ACC27(v, wp) do {                                                      \
    const float4* w4_ = reinterpret_cast<const float4*>(wp);                   \
    float4 q_;                                                                 \
    q_ = w4_[0]; acc[0]+=(v)*q_.x; acc[1]+=(v)*q_.y; acc[2]+=(v)*q_.z; acc[3]+=(v)*q_.w; \
    q_ = w4_[1]; acc[4]+=(v)*q_.x; acc[5]+=(v)*q_.y; acc[6]+=(v)*q_.z; acc[7]+=(v)*q_.w; \
    q_ = w4_[2]; acc[8]+=(v)*q_.x; acc[9]+=(v)*q_.y; acc[10]+=(v)*q_.z; acc[11]+=(v)*q_.w; \
    q_ = w4_[3]; acc[12]+=(v)*q_.x; acc[13]+=(v)*q_.y; acc[14]+=(v)*q_.z; acc[15]+=(v)*q_.w; \
    q_ = w4_[4]; acc[16]+=(v)*q_.x; acc[17]+=(v)*q_.y; acc[18]+=(v)*q_.z; acc[19]+=(v)*q_.w; \
    q_ = w4_[5]; acc[20]+=(v)*q_.x; acc[21]+=(v)*q_.y; acc[22]+=(v)*q_.z; acc[23]+=(v)*q_.w; \
    q_ = w4_[6]; acc[24]+=(v)*q_.x; acc[25]+=(v)*q_.y; acc[26]+=(v)*q_.z;     \
} while (0)

__global__ void k_offmod(const float* __restrict__ offset_w,
                         const float* __restrict__ offset_b,
                         const float* __restrict__ mod_w,
                         const float* __restrict__ mod_b) {
    // ws[tap_local][c][27 (+1 pad)] for 3 taps of one kernel row at a time
    __shared__ float ws[3][CC][28];
    int b = blockIdx.z;
    int h = blockIdx.y * 16 + (threadIdx.x >> 4);
    int w = blockIdx.x * 16 + (threadIdx.x & 15);

    float acc[27];
#pragma unroll
    for (int j = 0; j < 27; j++) acc[j] = 0.f;

    for (int tg = 0; tg < 3; ++tg) {           // tap row (dy = tg-1)
        __syncthreads();
        for (int idx = threadIdx.x; idx < 3 * CC * 27; idx += blockDim.x) {
            int tl = idx / (CC * 27);
            int r  = idx % (CC * 27);
            int c  = r / 27;
            int ch = r % 27;
            int t  = tg * 3 + tl;
            float wv = (ch < 18) ? offset_w[(ch * CC + c) * K2 + t]
                                 : mod_w[((ch - 18) * CC + c) * K2 + t];
            ws[tl][c][ch] = wv;
        }
        __syncthreads();

        int y = h + tg - 1;
        if (y < 0 || y >= HH) continue;
#pragma unroll
        for (int tl = 0; tl < 3; ++tl) {       // tap col (dx = tl-1)
            int xx = w + tl - 1;
            if (xx < 0 || xx >= WW) continue;
            const float4* row4 =
                reinterpret_cast<const float4*>(&g_xT[((b * HH + y) * WW + xx) * CC]);
#pragma unroll 2
            for (int c4 = 0; c4 < CC / 4; c4++) {
                float4 v4 = row4[c4];
                ACC27(v4.x, &ws[tl][c4 * 4 + 0][0]);
                ACC27(v4.y, &ws[tl][c4 * 4 + 1][0]);
                ACC27(v4.z, &ws[tl][c4 * 4 + 2][0]);
                ACC27(v4.w, &ws[tl][c4 * 4 + 3][0]);
            }
        }
    }

    int pix = (b * HH + h) * WW + w;
    float* op = &g_off[(size_t)pix * 18];
#pragma unroll
    for (int j = 0; j < 18; j++) op[j] = acc[j] + offset_b[j];

    float mm = 0.f;
#pragma unroll
    for (int j = 0; j < 9; j++) {
        float z = acc[18 + j] + mod_b[j];
        mm += 1.f / (1.f + expf(-z));
    }
    g_mm[pix] = mm * (1.f / 9.f);
}

// ---------------- kernel 3: deformable gather + 64x576 per-pixel GEMM --------
__global__ void __launch_bounds__(256) k_main(const float* __restrict__ bias,
                                              float* __restrict__ out) {
    __shared__ float wk[CC][OO];   // 16KB: weight slice for tap k, [c][o]
    __shared__ float ss[CC][32];   // 8KB : sampled values, [c][pix]

    int b  = blockIdx.z;
    int h  = blockIdx.y;
    int w0 = blockIdx.x * 32;
    int tid = threadIdx.x;

    // stage-A mapping: lane = pixel, warp covers 32 pixels for 8 channels
    int pix  = tid & 31;
    int cgrp = tid >> 5;          // 0..7 -> channels cgrp*8 .. +7
    int c0   = cgrp * 8;
    int wpix = w0 + pix;
    const float* offp = &g_off[(size_t)((b * HH + h) * WW + wpix) * 18];

    // GEMM mapping: 16x16 thread grid, 4 outputs x 2 pixels each
    int ty = tid >> 4, tx = tid & 15;
    int o0 = ty * 4, p0 = tx * 2;
    float acc[8];
#pragma unroll
    for (int i = 0; i < 8; i++) acc[i] = 0.f;

    for (int k = 0; k < K2; k++) {
        __syncthreads();   // previous GEMM done reading wk/ss

        // stage weight slice [c][o] (coalesced float4 copy)
        {
            const float4* src = reinterpret_cast<const float4*>(&g_w3[k * CC * OO]);
            float4* dst = reinterpret_cast<float4*>(&wk[0][0]);
            for (int i = tid; i < CC * OO / 4; i += 256) dst[i] = src[i];
        }

        // stage bilinear samples for this tap
        {
            float offy = offp[k];
            float offx = offp[9 + k];
            float sy = (float)(h + k / 3 - 1) + offy;
            float sx = (float)(wpix + k % 3 - 1) + offx;
            float fy0 = floorf(sy), fx0 = floorf(sx);
            int iy0 = (int)fy0, ix0 = (int)fx0;
            float ay = sy - fy0, ax = sx - fx0;
            float cwt[4];
            cwt[0] = (1.f - ay) * (1.f - ax);
            cwt[1] = (1.f - ay) * ax;
            cwt[2] = ay * (1.f - ax);
            cwt[3] = ay * ax;
            int cy[4] = {iy0, iy0, iy0 + 1, iy0 + 1};
            int cx[4] = {ix0, ix0 + 1, ix0, ix0 + 1};

            float v[8];
#pragma unroll
            for (int j = 0; j < 8; j++) v[j] = 0.f;
#pragma unroll
            for (int q = 0; q < 4; q++) {
                int iy = cy[q], ix = cx[q];
                if (iy >= 0 && iy < HH && ix >= 0 && ix < WW) {
                    const float4* p = reinterpret_cast<const float4*>(
                        &g_xT[((size_t)(b * HH + iy) * WW + ix) * CC + c0]);
                    float4 a = p[0], bq = p[1];
                    float wt = cwt[q];
                    v[0] += wt * a.x;  v[1] += wt * a.y;
                    v[2] += wt * a.z;  v[3] += wt * a.w;
                    v[4] += wt * bq.x; v[5] += wt * bq.y;
                    v[6] += wt * bq.z; v[7] += wt * bq.w;
                }
            }
#pragma unroll
            for (int j = 0; j < 8; j++) ss[c0 + j][pix] = v[j];
        }

        __syncthreads();

        // register-tiled GEMM: out[o][pix] += wk[c][o] * ss[c][pix]
#pragma unroll 8
        for (int c = 0; c < CC; c++) {
            float4 wv = *reinterpret_cast<const float4*>(&wk[c][o0]);
            float2 sv = *reinterpret_cast<const float2*>(&ss[c][p0]);
            acc[0] += wv.x * sv.x;  acc[1] += wv.x * sv.y;
            acc[2] += wv.y * sv.x;  acc[3] += wv.y * sv.y;
            acc[4] += wv.z * sv.x;  acc[5] += wv.z * sv.y;
            acc[6] += wv.w * sv.x;  acc[7] += wv.w * sv.y;
        }
    }

    // epilogue: * mod_mean + bias, write NCHW
    float mm0 = g_mm[(b * HH + h) * WW + w0 + p0];
    float mm1 = g_mm[(b * HH + h) * WW + w0 + p0 + 1];
#pragma unroll
    for (int i = 0; i < 4; i++) {
        float bo = bias[o0 + i];
        size_t base = ((size_t)(b * OO + o0 + i) * HH + h) * WW + w0;
        out[base + p0]     = acc[i * 2 + 0] * mm0 + bo;
        out[base + p0 + 1] = acc[i * 2 + 1] * mm1 + bo;
    }
}

// ---------------- launch -----------------------------------------------------
extern "C" void kernel_launch(void* const* d_in, const int* in_sizes, int n_in,
                              void* d_out, int out_size) {
    const float* x        = (const float*)d_in[0];
    const float* weight   = (const float*)d_in[1];
    const float* bias     = (const float*)d_in[2];
    const float* offset_w = (const float*)d_in[3];
    const float* offset_b = (const float*)d_in[4];
    const float* mod_w    = (const float*)d_in[5];
    const float* mod_b    = (const float*)d_in[6];
    float* out = (float*)d_out;

    k_transpose<<<BB * HH, 256>>>(x);
    k_wreorg<<<36, 256>>>(weight);
    k_offmod<<<dim3(WW / 16, HH / 16, BB), 256>>>(offset_w, offset_b, mod_w, mod_b);
    k_main<<<dim3(WW / 32, HH, BB), 256>>>(bias, out);
}

// round 2
// speedup vs baseline: 1.0965x; 1.0965x over previous
#include <cuda_runtime.h>
#include <math.h>

#define BB 4
#define CC 64
#define HH 128
#define WW 128
#define OO 64
#define KK 3
#define K2 9

// ---------------- scratch (device globals; no allocation allowed) ------------
__device__ float g_xT[BB*HH*WW*CC];     // x transposed to (B,H,W,C)   ~16.8MB
__device__ float g_off[BB*HH*WW*18];    // per-pixel packed offsets (9 y, 9 x)
__device__ float g_mm [BB*HH*WW];       // per-pixel modulation mean
__device__ float g_w3 [K2*CC*OO];       // weight reorganized [k][c][o]

// ---------------- kernel 0: NCHW -> NHWC transpose ---------------------------
__global__ void k_transpose(const float* __restrict__ x) {
    int b = blockIdx.x >> 7;        // gridDim.x = B*H = 512
    int h = blockIdx.x & 127;
    __shared__ float tile[CC][WW + 1];
    for (int idx = threadIdx.x; idx < CC * WW; idx += blockDim.x) {
        int c = idx >> 7, w = idx & 127;
        tile[c][w] = x[((b * CC + c) * HH + h) * WW + w];
    }
    __syncthreads();
    for (int idx = threadIdx.x; idx < CC * WW; idx += blockDim.x) {
        int w = idx >> 6, c = idx & 63;
        g_xT[((b * HH + h) * WW + w) * CC + c] = tile[c][w];
    }
}

// ---------------- kernel 1: weight reorg (O,C,3,3) -> [k][c][o] --------------
__global__ void k_wreorg(const float* __restrict__ weight) {
    for (int idx = blockIdx.x * blockDim.x + threadIdx.x; idx < K2 * CC * OO;
         idx += gridDim.x * blockDim.x) {
        int k = idx / (CC * OO);
        int r = idx % (CC * OO);
        int c = r / OO;
        int o = r % OO;
        g_w3[idx] = weight[(o * CC + c) * K2 + k];
    }
}

// ---------------- kernel 2: fused offset(18) + mod(9) 3x3 conv ---------------
#define ACC27(v, wp) do {                                                      \
    const float4* w4_ = reinterpret_cast<const float4*>(wp);                   \
    float4 q_;                                                                 \
    q_ = w4_[0]; acc[0]+=(v)*q_.x; acc[1]+=(v)*q_.y; acc[2]+=(v)*q_.z; acc[3]+=(v)*q_.w; \
    q_ = w4_[1]; acc[4]+=(v)*q_.x; acc[5]+=(v)*q_.y; acc[6]+=(v)*q_.z; acc[7]+=(v)*q_.w; \
    q_ = w4_[2]; acc[8]+=(v)*q_.x; acc[9]+=(v)*q_.y; acc[10]+=(v)*q_.z; acc[11]+=(v)*q_.w; \
    q_ = w4_[3]; acc[12]+=(v)*q_.x; acc[13]+=(v)*q_.y; acc[14]+=(v)*q_.z; acc[15]+=(v)*q_.w; \
    q_ = w4_[4]; acc[16]+=(v)*q_.x; acc[17]+=(v)*q_.y; acc[18]+=(v)*q_.z; acc[19]+=(v)*q_.w; \
    q_ = w4_[5]; acc[20]+=(v)*q_.x; acc[21]+=(v)*q_.y; acc[22]+=(v)*q_.z; acc[23]+=(v)*q_.w; \
    q_ = w4_[6]; acc[24]+=(v)*q_.x; acc[25]+=(v)*q_.y; acc[26]+=(v)*q_.z;     \
} while (0)

__global__ void k_offmod(const float* __restrict__ offset_w,
                         const float* __restrict__ offset_b,
                         const float* __restrict__ mod_w,
                         const float* __restrict__ mod_b) {
    // ws[tap_local][c][27 (+1 pad)] for 3 taps of one kernel row at a time
    __shared__ float ws[3][CC][28];
    int b = blockIdx.z;
    int h = blockIdx.y * 16 + (threadIdx.x >> 4);
    int w = blockIdx.x * 16 + (threadIdx.x & 15);

    float acc[27];
#pragma unroll
    for (int j = 0; j < 27; j++) acc[j] = 0.f;

    for (int tg = 0; tg < 3; ++tg) {           // tap row (dy = tg-1)
        __syncthreads();
        for (int idx = threadIdx.x; idx < 3 * CC * 27; idx += blockDim.x) {
            int tl = idx / (CC * 27);
            int r  = idx % (CC * 27);
            int c  = r / 27;
            int ch = r % 27;
            int t  = tg * 3 + tl;
            float wv = (ch < 18) ? offset_w[(ch * CC + c) * K2 + t]
                                 : mod_w[((ch - 18) * CC + c) * K2 + t];
            ws[tl][c][ch] = wv;
        }
        __syncthreads();

        int y = h + tg - 1;
        if (y < 0 || y >= HH) continue;
#pragma unroll
        for (int tl = 0; tl < 3; ++tl) {       // tap col (dx = tl-1)
            int xx = w + tl - 1;
            if (xx < 0 || xx >= WW) continue;
            const float4* row4 =
                reinterpret_cast<const float4*>(&g_xT[((b * HH + y) * WW + xx) * CC]);
#pragma unroll 2
            for (int c4 = 0; c4 < CC / 4; c4++) {
                float4 v4 = row4[c4];
                ACC27(v4.x, &ws[tl][c4 * 4 + 0][0]);
                ACC27(v4.y, &ws[tl][c4 * 4 + 1][0]);
                ACC27(v4.z, &ws[tl][c4 * 4 + 2][0]);
                ACC27(v4.w, &ws[tl][c4 * 4 + 3][0]);
            }
        }
    }

    int pix = (b * HH + h) * WW + w;
    float* op = &g_off[(size_t)pix * 18];
#pragma unroll
    for (int j = 0; j < 18; j++) op[j] = acc[j] + offset_b[j];

    float mm = 0.f;
#pragma unroll
    for (int j = 0; j < 9; j++) {
        float z = acc[18 + j] + mod_b[j];
        mm += 1.f / (1.f + expf(-z));
    }
    g_mm[pix] = mm * (1.f / 9.f);
}

// ---------------- kernel 3: deformable gather + row-tile GEMM ----------------
// Block = one image row (128 px) x all 64 outputs. 256 threads.
// Each thread computes 8 outputs x 4 pixels (32 accumulators).
// Per c-iteration: 2 broadcast LDS.128 (weights) + 1 LDS.128 (samples)
// feeding 32 FMAs -> 0.094 LDS-instr per FMA.
__global__ void __launch_bounds__(256, 3) k_main(const float* __restrict__ bias,
                                                 float* __restrict__ out) {
    __shared__ float wk[CC][OO];    // 16KB: weight slice for tap k, [c][o]
    __shared__ float ss[CC][WW];    // 32KB: sampled values, [c][pix]

    int h = blockIdx.x;
    int b = blockIdx.y;
    int tid = threadIdx.x;

    // gather mapping: 2 threads per pixel (each owns 32 channels)
    int gpix  = tid & 127;
    int ghalf = tid >> 7;           // 0 -> channels 0..31, 1 -> 32..63
    int gc0   = ghalf * 32;
    const float* offp = &g_off[(size_t)((b * HH + h) * WW + gpix) * 18];

    // GEMM mapping: warp = 8 outputs (broadcast weights), lane = 4 pixels
    int o0 = (tid >> 5) * 8;
    int p0 = (tid & 31) * 4;

    float acc[32];
#pragma unroll
    for (int i = 0; i < 32; i++) acc[i] = 0.f;

    for (int k = 0; k < K2; k++) {
        __syncthreads();   // previous GEMM done reading wk/ss

        // ---- stage weight slice [c][o] (coalesced float4 copy) ----
        {
            const float4* src = reinterpret_cast<const float4*>(&g_w3[k * CC * OO]);
            float4* dst = reinterpret_cast<float4*>(&wk[0][0]);
#pragma unroll
            for (int i = 0; i < CC * OO / 4 / 256; i++)
                dst[tid + i * 256] = src[tid + i * 256];
        }

        // ---- stage bilinear samples for this tap (32 channels/thread) ----
        {
            float offy = offp[k];
            float offx = offp[9 + k];
            float sy = (float)(h + k / 3 - 1) + offy;
            float sx = (float)(gpix + k % 3 - 1) + offx;
            float fy0 = floorf(sy), fx0 = floorf(sx);
            int iy0 = (int)fy0, ix0 = (int)fx0;
            float ay = sy - fy0, ax = sx - fx0;
            float cwt[4];
            cwt[0] = (1.f - ay) * (1.f - ax);
            cwt[1] = (1.f - ay) * ax;
            cwt[2] = ay * (1.f - ax);
            cwt[3] = ay * ax;
            const float4* cptr[4];
            bool cok[4];
#pragma unroll
            for (int q = 0; q < 4; q++) {
                int iy = iy0 + (q >> 1), ix = ix0 + (q & 1);
                cok[q] = (iy >= 0 && iy < HH && ix >= 0 && ix < WW);
                int iyc = cok[q] ? iy : 0;
                int ixc = cok[q] ? ix : 0;
                cptr[q] = reinterpret_cast<const float4*>(
                    &g_xT[((size_t)(b * HH + iyc) * WW + ixc) * CC + gc0]);
            }
#pragma unroll
            for (int ch = 0; ch < 4; ch++) {   // 4 chunks of 8 channels
                float v[8];
#pragma unroll
                for (int j = 0; j < 8; j++) v[j] = 0.f;
#pragma unroll
                for (int q = 0; q < 4; q++) {
                    if (cok[q]) {
                        float4 a0 = cptr[q][ch * 2];
                        float4 a1 = cptr[q][ch * 2 + 1];
                        float wt = cwt[q];
                        v[0] += wt * a0.x; v[1] += wt * a0.y;
                        v[2] += wt * a0.z; v[3] += wt * a0.w;
                        v[4] += wt * a1.x; v[5] += wt * a1.y;
                        v[6] += wt * a1.z; v[7] += wt * a1.w;
                    }
                }
                int cc = gc0 + ch * 8;
#pragma unroll
                for (int j = 0; j < 8; j++) ss[cc + j][gpix] = v[j];
            }
        }

        __syncthreads();

        // ---- register-tiled GEMM: acc[o][p] += wk[c][o] * ss[c][p] ----
#pragma unroll 4
        for (int c = 0; c < CC; c++) {
            float4 w0 = *reinterpret_cast<const float4*>(&wk[c][o0]);
            float4 w1 = *reinterpret_cast<const float4*>(&wk[c][o0 + 4]);
            float4 s  = *reinterpret_cast<const float4*>(&ss[c][p0]);
            acc[0]  += w0.x * s.x; acc[1]  += w0.x * s.y; acc[2]  += w0.x * s.z; acc[3]  += w0.x * s.w;
            acc[4]  += w0.y * s.x; acc[5]  += w0.y * s.y; acc[6]  += w0.y * s.z; acc[7]  += w0.y * s.w;
            acc[8]  += w0.z * s.x; acc[9]  += w0.z * s.y; acc[10] += w0.z * s.z; acc[11] += w0.z * s.w;
            acc[12] += w0.w * s.x; acc[13] += w0.w * s.y; acc[14] += w0.w * s.z; acc[15] += w0.w * s.w;
            acc[16] += w1.x * s.x; acc[17] += w1.x * s.y; acc[18] += w1.x * s.z; acc[19] += w1.x * s.w;
            acc[20] += w1.y * s.x; acc[21] += w1.y * s.y; acc[22] += w1.y * s.z; acc[23] += w1.y * s.w;
            acc[24] += w1.z * s.x; acc[25] += w1.z * s.y; acc[26] += w1.z * s.z; acc[27] += w1.z * s.w;
            acc[28] += w1.w * s.x; acc[29] += w1.w * s.y; acc[30] += w1.w * s.z; acc[31] += w1.w * s.w;
        }
    }

    // ---- epilogue: * mod_mean + bias, write NCHW ----
    float4 mmv = *reinterpret_cast<const float4*>(&g_mm[(size_t)((b * HH + h) * WW) + p0]);
#pragma unroll
    for (int r = 0; r < 8; r++) {
        float bo = bias[o0 + r];
        float4 res;
        res.x = acc[r * 4 + 0] * mmv.x + bo;
        res.y = acc[r * 4 + 1] * mmv.y + bo;
        res.z = acc[r * 4 + 2] * mmv.z + bo;
        res.w = acc[r * 4 + 3] * mmv.w + bo;
        *reinterpret_cast<float4*>(
            &out[((size_t)(b * OO + o0 + r) * HH + h) * WW + p0]) = res;
    }
}

// ---------------- launch -----------------------------------------------------
extern "C" void kernel_launch(void* const* d_in, const int* in_sizes, int n_in,
                              void* d_out, int out_size) {
    const float* x        = (const float*)d_in[0];
    const float* weight   = (const float*)d_in[1];
    const float* bias     = (const float*)d_in[2];
    const float* offset_w = (const float*)d_in[3];
    const float* offset_b = (const float*)d_in[4];
    const float* mod_w    = (const float*)d_in[5];
    const float* mod_b    = (const float*)d_in[6];
    float* out = (float*)d_out;

    k_transpose<<<BB * HH, 256>>>(x);
    k_wreorg<<<36, 256>>>(weight);
    k_offmod<<<dim3(WW / 16, HH / 16, BB), 256>>>(offset_w, offset_b, mod_w, mod_b);
    k_main<<<dim3(HH, BB), 256>>>(bias, out);
}